// round 9
// baseline (speedup 1.0000x reference)
#include <cuda_runtime.h>

typedef unsigned long long ull;

// ---------------- problem constants ----------------
#define BATCH   128
#define HH      384
#define WW      384
#define OW      385
#define SH      58
#define STRIPS  7
#define NPART   (STRIPS*BATCH)
#define NTHREADS 224        // 7 warps; thread t owns cols 2t, 2t+1

// ---------------- shared layout (ull units) ----------------
// raw ring: 10 slots * 400 ull. Per slot: E half [0,200): col 2c at c+2;
//           O half [200,400): col 2c+1 at 200+c+2. Pads stay zero.
#define RAW_ULL  4000
#define ZERO_ULL RAW_ULL
#define SMEM_BYTES ((ZERO_ULL + 18) * 8)

__device__ float g_part[NPART * 5];

// ---------------- packed f32x2 helpers ----------------
__device__ __forceinline__ ull f2pack(float lo, float hi) {
    ull r; asm("mov.b64 %0,{%1,%2};" : "=l"(r) : "f"(lo), "f"(hi)); return r;
}
__device__ __forceinline__ void f2unpack(ull v, float& lo, float& hi) {
    asm("mov.b64 {%0,%1},%2;" : "=f"(lo), "=f"(hi) : "l"(v));
}
__device__ __forceinline__ ull f2add(ull a, ull b) {
    ull r; asm("add.rn.f32x2 %0,%1,%2;" : "=l"(r) : "l"(a), "l"(b)); return r;
}
__device__ __forceinline__ ull f2mul(ull a, ull b) {
    ull r; asm("mul.rn.f32x2 %0,%1,%2;" : "=l"(r) : "l"(a), "l"(b)); return r;
}
__device__ __forceinline__ ull f2fma(ull a, ull b, ull c) {
    ull r; asm("fma.rn.f32x2 %0,%1,%2,%3;" : "=l"(r) : "l"(a), "l"(b), "l"(c)); return r;
}
#define F2NEG1 0xBF800000BF800000ULL   // (-1.0f, -1.0f)

__device__ __forceinline__ float hadd(ull v) { float lo, hi; f2unpack(v, lo, hi); return lo + hi; }

// h7 of one stored row (slot base eb) for cols 2t (out: s7,m7) and 2t+1 (s7b,m7b)
__device__ __forceinline__ void h7c(const ull* eb, int t,
                                    ull& s7, ull& m7, ull& s7b, ull& m7b)
{
    ull o_m2 = eb[200 + t],     e_m1 = eb[t + 1],
        o_m1 = eb[200 + t + 1], e0   = eb[t + 2],
        o0   = eb[200 + t + 2], e1   = eb[t + 3],
        o1   = eb[200 + t + 3], e2   = eb[t + 4];
    float xa,ya,xb2,yb2,xcv,ycv,xd,yd,xe,ye,xf,yf,xg,yg,xh,yh;
    f2unpack(o_m2,xa,ya);  f2unpack(e_m1,xb2,yb2);
    f2unpack(o_m1,xcv,ycv); f2unpack(e0,xd,yd);
    f2unpack(o0,xe,ye);    f2unpack(e1,xf,yf);
    f2unpack(o1,xg,yg);    f2unpack(e2,xh,yh);

    s7 = f2add(f2add(f2add(o_m2, e_m1), f2add(o_m1, e0)),
               f2add(f2add(o0, e1), o1));
    ull sq7 = f2fma(o_m2,o_m2, f2fma(e_m1,e_m1, f2fma(o_m1,o_m1,
              f2fma(e0,e0, f2fma(o0,o0, f2fma(e1,e1, f2mul(o1,o1)))))));
    float Q7  = hadd(sq7);
    float xy7 = fmaf(xa,ya, fmaf(xb2,yb2, fmaf(xcv,ycv,
                fmaf(xd,yd, fmaf(xe,ye, fmaf(xf,yf, xg*yg))))));
    s7b = f2add(f2fma(o_m2, F2NEG1, s7), e2);
    float Q7b  = Q7 - fmaf(xa,xa, ya*ya) + fmaf(xh,xh, yh*yh);
    float xy7b = fmaf(xh, yh, fmaf(-xa, ya, xy7));
    m7  = f2pack(Q7,  xy7);
    m7b = f2pack(Q7b, xy7b);
}

// h4 of one stored row for cols 2t and 2t+1
__device__ __forceinline__ void h4c(const ull* fb, int t,
                                    ull& s4, ull& m4, ull& s4b, ull& m4b)
{
    ull e_m1 = fb[t + 1], o_m1 = fb[200 + t + 1],
        e0   = fb[t + 2], o0   = fb[200 + t + 2],
        e1   = fb[t + 3];
    float xa,ya,xb2,yb2,xcv,ycv,xd,yd,xe,ye;
    f2unpack(e_m1,xa,ya); f2unpack(o_m1,xb2,yb2);
    f2unpack(e0,xcv,ycv); f2unpack(o0,xd,yd);
    f2unpack(e1,xe,ye);
    s4 = f2add(f2add(e_m1, o_m1), f2add(e0, o0));
    ull sq4 = f2fma(e_m1,e_m1, f2fma(o_m1,o_m1, f2fma(e0,e0, f2mul(o0,o0))));
    float Q4  = hadd(sq4);
    float xy4 = fmaf(xa,ya, fmaf(xb2,yb2, fmaf(xcv,ycv, xd*yd)));
    s4b = f2add(f2fma(e_m1, F2NEG1, s4), e1);
    float Q4b  = Q4 - fmaf(xa,xa, ya*ya) + fmaf(xe,xe, ye*ye);
    float xy4b = fmaf(xe, ye, fmaf(-xa, ya, xy4));
    m4  = f2pack(Q4,  xy4);
    m4b = f2pack(Q4b, xy4b);
}

// SSIM numerator/denominator (scalar; Q = Sxx+Syy). n=k*k, c1=C1*n^2, c2=C2*n^2.
__device__ __forceinline__ float ssim_nd(float Sx, float Sy, float Q, float xy,
                                         float n, float c1, float c2, float& D)
{
    float t  = Sx * Sy;
    float A1 = fmaf(2.f, t, c1);
    float u  = fmaf(n, xy, -t);
    float A2 = fmaf(2.f, u, c2);
    float pq = fmaf(Sy, Sy, Sx * Sx);
    float B1 = pq + c1;
    float B2 = fmaf(n, Q, -pq) + c2;
    D = B1 * B2;
    return A1 * A2;
}

__global__ __launch_bounds__(NTHREADS, 4)
void msssim_main_kernel(const float* __restrict__ X,
                        const float* __restrict__ Y,
                        const float* __restrict__ DR)
{
    extern __shared__ ull sm8[];
    ull*   raw = sm8;                       // [10][400]
    float* red = (float*)(sm8 + ZERO_ULL);

    const int tid = threadIdx.x;
    const int b   = blockIdx.y;
    const int i0  = blockIdx.x * SH;
    const int i1  = min(i0 + SH, OW);
    const int i1k = min(i1, HH);
    const int ibase = i0 - 6;
    const int M   = i1 - ibase;             // 64 (43 last strip)
    const int nGroup = (M + 9) / 10;

    const float dr = DR[b];
    const float C1 = (0.01f * dr) * (0.01f * dr);
    const float C2 = (0.03f * dr) * (0.03f * dr);
    const float c1_2 = C1 * 16.f,   c2_2 = C2 * 16.f;
    const float c1_4 = C1 * 256.f,  c2_4 = C2 * 256.f;
    const float c1_7 = C1 * 2401.f, c2_7 = C2 * 2401.f;

    // zero all ring smem (invalid-row slots and pads must read as zeros)
    for (int k = tid; k < ZERO_ULL; k += NTHREADS) sm8[k] = 0ULL;

    const int  t    = tid;
    const bool act  = (t < 193);
    const bool full = (t < 192);
    const float msk1 = full ? 1.f : 0.f;

    ull v7s0 = 0, v7m0 = 0, v7s1 = 0, v7m1 = 0;
    ull v4s0 = 0, v4m0 = 0, v4s1 = 0, v4m1 = 0;
    float acc1 = 0.f, acc2 = 0.f, acc4 = 0.f, acc7 = 0.f, accL = 0.f;

    const float2* X2 = (const float2*)X + (size_t)b * (HH * WW / 2);
    const float2* Y2 = (const float2*)Y + (size_t)b * (HH * WW / 2);

    float2 zz; zz.x = 0.f; zz.y = 0.f;
    float2 cxA = zz, cyA = zz, cxB = zz, cyB = zz;   // rows ibase+3, ibase+4
    if (full) {
        int rA = ibase + 3;
        if ((unsigned)rA < HH) { cxA = X2[rA * 192 + t]; cyA = Y2[rA * 192 + t]; }
        if ((unsigned)(rA + 1) < HH) { cxB = X2[(rA + 1) * 192 + t]; cyB = Y2[(rA + 1) * 192 + t]; }
    }
    __syncthreads();    // zero-init visible

    for (int g = 0; g < nGroup; ++g) {
        const int gm = g * 10;
        #pragma unroll
        for (int bq = 0; bq < 5; ++bq) {
            const int m0 = gm + bq * 2;

            // prefetch next pair rows (ibase+m0+5, +6)
            float2 pxA = zz, pyA = zz, pxB = zz, pyB = zz;
            if (full) {
                int rn = ibase + m0 + 5;
                if ((unsigned)rn < HH) { pxA = X2[rn * 192 + t]; pyA = Y2[rn * 192 + t]; }
                if ((unsigned)(rn + 1) < HH) { pxB = X2[(rn+1) * 192 + t]; pyB = Y2[(rn+1) * 192 + t]; }
            }

            // k=1 SSIM for the two current rows (register values; one divide each)
            if (full) {
                int rA = ibase + m0 + 3;
                if (rA >= i0 && rA < i1k) {
                    float a0 = fmaf(2.f, cxA.x * cyA.x, C1);
                    float b0 = fmaf(cxA.x, cxA.x, fmaf(cyA.x, cyA.x, C1));
                    float a1 = fmaf(2.f, cxA.y * cyA.y, C1);
                    float b1 = fmaf(cxA.y, cxA.y, fmaf(cyA.y, cyA.y, C1));
                    acc1 += __fdividef(fmaf(a0, b1, a1 * b0), b0 * b1);
                }
                if (rA + 1 >= i0 && rA + 1 < i1k) {
                    float a0 = fmaf(2.f, cxB.x * cyB.x, C1);
                    float b0 = fmaf(cxB.x, cxB.x, fmaf(cyB.x, cyB.x, C1));
                    float a1 = fmaf(2.f, cxB.y * cyB.y, C1);
                    float b1 = fmaf(cxB.y, cxB.y, fmaf(cyB.y, cyB.y, C1));
                    acc1 += __fdividef(fmaf(a0, b1, a1 * b0), b0 * b1);
                }
            }

            // store current rows (zeros when invalid keep ring clean)
            if (full) {
                ull* pa = raw + (bq * 2) * 400;
                pa[t + 2]       = f2pack(cxA.x, cyA.x);
                pa[200 + t + 2] = f2pack(cxA.y, cyA.y);
                ull* pb = raw + (bq * 2 + 1) * 400;
                pb[t + 2]       = f2pack(cxB.x, cyB.x);
                pb[200 + t + 2] = f2pack(cxB.y, cyB.y);
            }
            __syncthreads();

            #pragma unroll
            for (int s = 0; s < 2; ++s) {
                const int u = bq * 2 + s;           // compile-time slot
                const int m = gm + u;
                const int i = ibase + m;

                if (act) {
                    // ---- v7 slide: + h7(row r, slot u) − h7(row r-7, slot (u+3)%10) ----
                    {
                        ull s7n, m7n, s7nb, m7nb;
                        h7c(raw + u * 400, t, s7n, m7n, s7nb, m7nb);
                        ull s7o, m7o, s7ob, m7ob;
                        h7c(raw + ((u + 3) % 10) * 400, t, s7o, m7o, s7ob, m7ob);
                        v7s0 = f2fma(s7o,  F2NEG1, f2add(v7s0, s7n));
                        v7m0 = f2fma(m7o,  F2NEG1, f2add(v7m0, m7n));
                        v7s1 = f2fma(s7ob, F2NEG1, f2add(v7s1, s7nb));
                        v7m1 = f2fma(m7ob, F2NEG1, f2add(v7m1, m7nb));
                    }
                    // ---- v4 slide: + h4(row i+1, slot (u+8)%10) − h4(row i-3, slot (u+4)%10) ----
                    {
                        ull s4n, m4n, s4nb, m4nb;
                        h4c(raw + ((u + 8) % 10) * 400, t, s4n, m4n, s4nb, m4nb);
                        ull s4o, m4o, s4ob, m4ob;
                        h4c(raw + ((u + 4) % 10) * 400, t, s4o, m4o, s4ob, m4ob);
                        v4s0 = f2fma(s4o,  F2NEG1, f2add(v4s0, s4n));
                        v4m0 = f2fma(m4o,  F2NEG1, f2add(v4m0, m4n));
                        v4s1 = f2fma(s4ob, F2NEG1, f2add(v4s1, s4nb));
                        v4m1 = f2fma(m4ob, F2NEG1, f2add(v4m1, m4nb));
                    }

                    // ---- emit output row i ----
                    if (i >= i0 && i < i1) {
                        float Sx, Sy, Qv, xyv, D0, D1;
                        // k=2 direct from raw rows i-1 (slot (u+6)%10), i ((u+7)%10)
                        const ull* ra_ = raw + ((u + 6) % 10) * 400;
                        const ull* rb_ = raw + ((u + 7) % 10) * 400;
                        ull a_om1 = ra_[200 + t + 1], a_e0 = ra_[t + 2], a_o0 = ra_[200 + t + 2];
                        ull b_om1 = rb_[200 + t + 1], b_e0 = rb_[t + 2], b_o0 = rb_[200 + t + 2];
                        float axa,aya,axb,ayb,axc,ayc,bxa,bya,bxb,byb,bxc,byc;
                        f2unpack(a_om1,axa,aya); f2unpack(a_e0,axb,ayb); f2unpack(a_o0,axc,ayc);
                        f2unpack(b_om1,bxa,bya); f2unpack(b_e0,bxb,byb); f2unpack(b_o0,bxc,byc);

                        ull s2 = f2add(f2add(a_om1, a_e0), f2add(b_om1, b_e0));
                        ull sq2 = f2fma(a_om1,a_om1, f2fma(a_e0,a_e0,
                                  f2fma(b_om1,b_om1, f2mul(b_e0,b_e0))));
                        float Q20  = hadd(sq2);
                        float xy20 = fmaf(axa,aya, fmaf(axb,ayb, fmaf(bxa,bya, bxb*byb)));
                        ull s2b = f2add(f2add(a_e0, a_o0), f2add(b_e0, b_o0));
                        ull sq2b = f2fma(a_e0,a_e0, f2fma(a_o0,a_o0,
                                   f2fma(b_e0,b_e0, f2mul(b_o0,b_o0))));
                        float Q21  = hadd(sq2b);
                        float xy21 = fmaf(axb,ayb, fmaf(axc,ayc, fmaf(bxb,byb, bxc*byc)));

                        f2unpack(s2, Sx, Sy);
                        float N0 = ssim_nd(Sx, Sy, Q20, xy20, 4.f, c1_2, c2_2, D0);
                        f2unpack(s2b, Sx, Sy);
                        float N1 = ssim_nd(Sx, Sy, Q21, xy21, 4.f, c1_2, c2_2, D1) * msk1;
                        acc2 += __fdividef(fmaf(N0, D1, N1 * D0), D0 * D1);

                        f2unpack(v4s0, Sx, Sy); f2unpack(v4m0, Qv, xyv);
                        N0 = ssim_nd(Sx, Sy, Qv, xyv, 16.f, c1_4, c2_4, D0);
                        f2unpack(v4s1, Sx, Sy); f2unpack(v4m1, Qv, xyv);
                        N1 = ssim_nd(Sx, Sy, Qv, xyv, 16.f, c1_4, c2_4, D1) * msk1;
                        acc4 += __fdividef(fmaf(N0, D1, N1 * D0), D0 * D1);

                        if (full && i < HH) {
                            f2unpack(v7s0, Sx, Sy); f2unpack(v7m0, Qv, xyv);
                            N0 = ssim_nd(Sx, Sy, Qv, xyv, 49.f, c1_7, c2_7, D0);
                            accL += fabsf(Sx - Sy);
                            f2unpack(v7s1, Sx, Sy); f2unpack(v7m1, Qv, xyv);
                            N1 = ssim_nd(Sx, Sy, Qv, xyv, 49.f, c1_7, c2_7, D1);
                            accL += fabsf(Sx - Sy);
                            acc7 += __fdividef(fmaf(N0, D1, N1 * D0), D0 * D1);
                        }
                    }
                }
            }
            cxA = pxA; cyA = pyA; cxB = pxB; cyB = pyB;
        }
    }

    // ---------------- deterministic block reduction ----------------
    #pragma unroll
    for (int o = 16; o > 0; o >>= 1) {
        acc1 += __shfl_down_sync(0xFFFFFFFFu, acc1, o);
        acc2 += __shfl_down_sync(0xFFFFFFFFu, acc2, o);
        acc4 += __shfl_down_sync(0xFFFFFFFFu, acc4, o);
        acc7 += __shfl_down_sync(0xFFFFFFFFu, acc7, o);
        accL += __shfl_down_sync(0xFFFFFFFFu, accL, o);
    }
    __syncthreads();
    const int w = tid >> 5, lane = tid & 31;
    if (lane == 0) {
        red[w*5 + 0] = acc1; red[w*5 + 1] = acc2; red[w*5 + 2] = acc4;
        red[w*5 + 3] = acc7; red[w*5 + 4] = accL;
    }
    __syncthreads();
    if (tid == 0) {
        float s0 = 0.f, s1 = 0.f, s2 = 0.f, s3 = 0.f, s4 = 0.f;
        for (int ww = 0; ww < 7; ++ww) {
            s0 += red[ww*5 + 0]; s1 += red[ww*5 + 1]; s2 += red[ww*5 + 2];
            s3 += red[ww*5 + 3]; s4 += red[ww*5 + 4];
        }
        const int pb = (b * STRIPS + blockIdx.x) * 5;
        g_part[pb + 0] = s0; g_part[pb + 1] = s1; g_part[pb + 2] = s2;
        g_part[pb + 3] = s3; g_part[pb + 4] = s4;
    }
}

__global__ void msssim_reduce_kernel(float* __restrict__ out)
{
    __shared__ double red[256][5];
    double a0 = 0, a1 = 0, a2 = 0, a3 = 0, a4 = 0;
    for (int idx = threadIdx.x; idx < NPART; idx += 256) {
        a0 += (double)g_part[idx*5 + 0];
        a1 += (double)g_part[idx*5 + 1];
        a2 += (double)g_part[idx*5 + 2];
        a3 += (double)g_part[idx*5 + 3];
        a4 += (double)g_part[idx*5 + 4];
    }
    red[threadIdx.x][0] = a0; red[threadIdx.x][1] = a1; red[threadIdx.x][2] = a2;
    red[threadIdx.x][3] = a3; red[threadIdx.x][4] = a4;
    __syncthreads();
    for (int s = 128; s > 0; s >>= 1) {
        if (threadIdx.x < s) {
            #pragma unroll
            for (int q = 0; q < 5; ++q) red[threadIdx.x][q] += red[threadIdx.x + s][q];
        }
        __syncthreads();
    }
    if (threadIdx.x == 0) {
        const double n384 = (double)BATCH * 384.0 * 384.0;
        const double n385 = (double)BATCH * 385.0 * 385.0;
        double m1 = red[0][0] / n384;
        double m2 = red[0][1] / n385;
        double m4 = red[0][2] / n385;
        double m7 = red[0][3] / n384;
        double l1 = red[0][4] / (49.0 * n384);
        double loss = 0.84 * (1.0 - m1 * m2 * m4 * m7) + 0.16 * l1;
        out[0] = (float)loss;
    }
}

// one pad launch keeps ncu's "-s 5 -c 1" landing on the MAIN kernel
__global__ void msssim_noop_kernel() {}

extern "C" void kernel_launch(void* const* d_in, const int* in_sizes, int n_in,
                              void* d_out, int out_size)
{
    (void)in_sizes; (void)n_in; (void)out_size;
    const float* X  = (const float*)d_in[0];
    const float* Y  = (const float*)d_in[1];
    const float* DR = (const float*)d_in[2];

    cudaFuncSetAttribute(msssim_main_kernel,
                         cudaFuncAttributeMaxDynamicSharedMemorySize, SMEM_BYTES);

    dim3 grid(STRIPS, BATCH);
    msssim_main_kernel<<<grid, NTHREADS, SMEM_BYTES>>>(X, Y, DR);
    msssim_reduce_kernel<<<1, 256>>>((float*)d_out);
    msssim_noop_kernel<<<1, 32>>>();
}

// round 10
// speedup vs baseline: 1.1506x; 1.1506x over previous
#include <cuda_runtime.h>

typedef unsigned long long ull;

// ---------------- problem constants ----------------
#define BATCH   128
#define HH      384
#define WW      384
#define OW      385
#define SH      58
#define STRIPS  7
#define NPART   (STRIPS*BATCH)
#define NTHREADS 224        // 7 warps; thread t owns cols 2t, 2t+1

// ---------------- shared layout ----------------
// raw ring: 8 slots, each 197 ulonglong2 entries. Entry c+2 holds cols (2c,2c+1):
//   .x = pack(x_{2c}, y_{2c}), .y = pack(x_{2c+1}, y_{2c+1}). Entries 0,1 and
//   194..196 are zero pads (t=192 overreads stay in-slot).
// r7 ring : 8 slots, each 386 ulonglong2: col j0 entry = slot*386 + t,
//   col j1 entry = slot*386 + 193 + t. Entry = {(Sx,Sy) packed, (Q,xy) packed}.
#define RAW_SLOT 197
#define R7_SLOT  386
#define RAW_U2   (8*RAW_SLOT)
#define R7_U2    (8*R7_SLOT)
#define ZERO_ULL ((RAW_U2 + R7_U2) * 2)
#define SMEM_BYTES (ZERO_ULL * 8 + 160)

__device__ float g_part[NPART * 5];

// ---------------- packed f32x2 helpers ----------------
__device__ __forceinline__ ull f2pack(float lo, float hi) {
    ull r; asm("mov.b64 %0,{%1,%2};" : "=l"(r) : "f"(lo), "f"(hi)); return r;
}
__device__ __forceinline__ void f2unpack(ull v, float& lo, float& hi) {
    asm("mov.b64 {%0,%1},%2;" : "=f"(lo), "=f"(hi) : "l"(v));
}
__device__ __forceinline__ ull f2add(ull a, ull b) {
    ull r; asm("add.rn.f32x2 %0,%1,%2;" : "=l"(r) : "l"(a), "l"(b)); return r;
}
__device__ __forceinline__ ull f2mul(ull a, ull b) {
    ull r; asm("mul.rn.f32x2 %0,%1,%2;" : "=l"(r) : "l"(a), "l"(b)); return r;
}
__device__ __forceinline__ ull f2fma(ull a, ull b, ull c) {
    ull r; asm("fma.rn.f32x2 %0,%1,%2,%3;" : "=l"(r) : "l"(a), "l"(b), "l"(c)); return r;
}
#define F2NEG1 0xBF800000BF800000ULL   // (-1.0f, -1.0f)

__device__ __forceinline__ float hadd(ull v) { float lo, hi; f2unpack(v, lo, hi); return lo + hi; }

// SSIM numerator/denominator (scalar; Q = Sxx+Syy). n=k*k, c1=C1*n^2, c2=C2*n^2.
__device__ __forceinline__ float ssim_nd(float Sx, float Sy, float Q, float xy,
                                         float n, float c1, float c2, float& D)
{
    float t  = Sx * Sy;
    float A1 = fmaf(2.f, t, c1);
    float u  = fmaf(n, xy, -t);
    float A2 = fmaf(2.f, u, c2);
    float pq = fmaf(Sy, Sy, Sx * Sx);
    float B1 = pq + c1;
    float B2 = fmaf(n, Q, -pq) + c2;
    D = B1 * B2;
    return A1 * A2;
}

__global__ __launch_bounds__(NTHREADS, 3)
void msssim_main_kernel(const float* __restrict__ X,
                        const float* __restrict__ Y,
                        const float* __restrict__ DR)
{
    extern __shared__ ull sm8[];
    ulonglong2* raw2 = (ulonglong2*)sm8;           // [8][197]
    ulonglong2* r72  = raw2 + RAW_U2;              // [8][386]
    float*      red  = (float*)(sm8 + ZERO_ULL);

    const int tid = threadIdx.x;
    const int b   = blockIdx.y;
    const int i0  = blockIdx.x * SH;
    const int i1  = min(i0 + SH, OW);
    const int i1k = min(i1, HH);
    const int ibase = i0 - 6;
    const int M   = i1 - ibase;                    // 64 (43 last strip)
    const int nOct = (M + 7) >> 3;

    const float dr = DR[b];
    const float C1 = (0.01f * dr) * (0.01f * dr);
    const float C2 = (0.03f * dr) * (0.03f * dr);
    const float c1_2 = C1 * 16.f,   c2_2 = C2 * 16.f;
    const float c1_4 = C1 * 256.f,  c2_4 = C2 * 256.f;
    const float c1_7 = C1 * 2401.f, c2_7 = C2 * 2401.f;

    // zero all ring smem (pads and invalid rows must read as zeros)
    for (int k = tid; k < ZERO_ULL; k += NTHREADS) sm8[k] = 0ULL;

    const int  t    = tid;
    const bool act  = (t < 193);
    const bool full = (t < 192);
    const float msk1 = full ? 1.f : 0.f;

    // h4 register ring (4 slots, 2 cols): s packed + (Q,xy) packed
    ull h4s0[4], h4m0[4], h4s1[4], h4m1[4];
    #pragma unroll
    for (int q = 0; q < 4; ++q) { h4s0[q]=0; h4m0[q]=0; h4s1[q]=0; h4m1[q]=0; }

    ull v7s0 = 0, v7m0 = 0, v7s1 = 0, v7m1 = 0;
    float acc1 = 0.f, acc2 = 0.f, acc4 = 0.f, acc7 = 0.f, accL = 0.f;

    const float2* X2 = (const float2*)X + (size_t)b * (HH * WW / 2);
    const float2* Y2 = (const float2*)Y + (size_t)b * (HH * WW / 2);

    float2 zz; zz.x = 0.f; zz.y = 0.f;
    float2 cxA = zz, cyA = zz, cxB = zz, cyB = zz;   // rows ibase+3, +4
    if (full) {
        int rA = ibase + 3;
        if ((unsigned)rA < HH) { cxA = X2[rA * 192 + t]; cyA = Y2[rA * 192 + t]; }
        if ((unsigned)(rA + 1) < HH) { cxB = X2[(rA + 1) * 192 + t]; cyB = Y2[(rA + 1) * 192 + t]; }
    }
    __syncthreads();    // zero-init visible

    for (int mo = 0; mo < nOct; ++mo) {
        #pragma unroll
        for (int sb = 0; sb < 4; ++sb) {
            const int m0 = (mo << 3) + (sb << 1);

            // prefetch next pair rows (ibase+m0+5, +6)
            float2 pxA = zz, pyA = zz, pxB = zz, pyB = zz;
            if (full) {
                int rn = ibase + m0 + 5;
                if ((unsigned)rn < HH) { pxA = X2[rn * 192 + t]; pyA = Y2[rn * 192 + t]; }
                if ((unsigned)(rn + 1) < HH) { pxB = X2[(rn+1) * 192 + t]; pyB = Y2[(rn+1) * 192 + t]; }
            }
            // store current pair rows into slots sb*2, sb*2+1 (zeros when invalid)
            if (full) {
                ulonglong2 v;
                v.x = f2pack(cxA.x, cyA.x); v.y = f2pack(cxA.y, cyA.y);
                raw2[(sb * 2) * RAW_SLOT + t + 2] = v;
                v.x = f2pack(cxB.x, cyB.x); v.y = f2pack(cxB.y, cyB.y);
                raw2[(sb * 2 + 1) * RAW_SLOT + t + 2] = v;
            }
            __syncthreads();

            #pragma unroll
            for (int s = 0; s < 2; ++s) {
                const int u = sb * 2 + s;          // compile-time slot
                const int m = (mo << 3) + u;
                const int i = ibase + m;
                const int r = i + 3;
                const float2 xc = s ? cxB : cxA;
                const float2 yc = s ? cyB : cyA;

                // ---- k=1 SSIM for row r (register data, one divide) ----
                if (full && r >= i0 && r < i1k) {
                    float a0 = fmaf(2.f, xc.x * yc.x, C1);
                    float b0 = fmaf(xc.x, xc.x, fmaf(yc.x, yc.x, C1));
                    float a1 = fmaf(2.f, xc.y * yc.y, C1);
                    float b1 = fmaf(xc.y, xc.y, fmaf(yc.y, yc.y, C1));
                    acc1 += __fdividef(fmaf(a0, b1, a1 * b0), b0 * b1);
                }

                if (act) {
                    // ---- h7 for row r (slot u, 5x LDS.128), v7 slide via r7 ring ----
                    {
                        const ulonglong2* eb = raw2 + u * RAW_SLOT + t;
                        ulonglong2 pm2 = eb[0], pm1 = eb[1], p0 = eb[2],
                                   pp1 = eb[3], pp2 = eb[4];
                        ull o_m2 = pm2.y, e_m1 = pm1.x, o_m1 = pm1.y,
                            e0 = p0.x, o0 = p0.y, e1 = pp1.x, o1 = pp1.y, e2 = pp2.x;
                        float xa,ya,xb2,yb2,xcv,ycv,xd,yd,xe,ye,xf,yf,xg,yg,xh,yh;
                        f2unpack(o_m2,xa,ya);  f2unpack(e_m1,xb2,yb2);
                        f2unpack(o_m1,xcv,ycv); f2unpack(e0,xd,yd);
                        f2unpack(o0,xe,ye);    f2unpack(e1,xf,yf);
                        f2unpack(o1,xg,yg);    f2unpack(e2,xh,yh);

                        ull s7 = f2add(f2add(f2add(o_m2, e_m1), f2add(o_m1, e0)),
                                       f2add(f2add(o0, e1), o1));
                        ull sq7 = f2fma(o_m2,o_m2, f2fma(e_m1,e_m1, f2fma(o_m1,o_m1,
                                  f2fma(e0,e0, f2fma(o0,o0, f2fma(e1,e1, f2mul(o1,o1)))))));
                        float Q7  = hadd(sq7);
                        float xy7 = fmaf(xa,ya, fmaf(xb2,yb2, fmaf(xcv,ycv,
                                    fmaf(xd,yd, fmaf(xe,ye, fmaf(xf,yf, xg*yg))))));
                        ull   s7b = f2add(f2fma(o_m2, F2NEG1, s7), e2);
                        float Q7b  = Q7 - fmaf(xa,xa, ya*ya) + fmaf(xh,xh, yh*yh);
                        float xy7b = fmaf(xh, yh, fmaf(-xa, ya, xy7));
                        ull m7  = f2pack(Q7,  xy7);
                        ull m7b = f2pack(Q7b, xy7b);

                        // old h7 (row m-7) lives at slot (u+1)&7; write new at slot u
                        const int so = ((u + 1) & 7) * R7_SLOT;
                        const int sn = u * R7_SLOT;
                        ulonglong2 o0v = r72[so + t];
                        ulonglong2 o1v = r72[so + 193 + t];
                        ulonglong2 nv;
                        nv.x = s7;  nv.y = m7;  r72[sn + t] = nv;
                        nv.x = s7b; nv.y = m7b; r72[sn + 193 + t] = nv;
                        v7s0 = f2fma(o0v.x, F2NEG1, f2add(v7s0, s7));
                        v7m0 = f2fma(o0v.y, F2NEG1, f2add(v7m0, m7));
                        v7s1 = f2fma(o1v.x, F2NEG1, f2add(v7s1, s7b));
                        v7m1 = f2fma(o1v.y, F2NEG1, f2add(v7m1, m7b));
                    }

                    // ---- h4 for row i+1 (slot (u+6)&7, 3x LDS.128) -> reg slot u&3 ----
                    {
                        const ulonglong2* fb = raw2 + ((u + 6) & 7) * RAW_SLOT + t;
                        ulonglong2 pm1 = fb[1], p0 = fb[2], pp1 = fb[3];
                        ull e_m1 = pm1.x, o_m1 = pm1.y, e0 = p0.x, o0 = p0.y, e1 = pp1.x;
                        float xa,ya,xb2,yb2,xcv,ycv,xd,yd,xe,ye;
                        f2unpack(e_m1,xa,ya); f2unpack(o_m1,xb2,yb2);
                        f2unpack(e0,xcv,ycv); f2unpack(o0,xd,yd);
                        f2unpack(e1,xe,ye);
                        ull s4 = f2add(f2add(e_m1, o_m1), f2add(e0, o0));
                        ull sq4 = f2fma(e_m1,e_m1, f2fma(o_m1,o_m1, f2fma(e0,e0, f2mul(o0,o0))));
                        float Q4  = hadd(sq4);
                        float xy4 = fmaf(xa,ya, fmaf(xb2,yb2, fmaf(xcv,ycv, xd*yd)));
                        h4s0[u & 3] = s4;
                        h4m0[u & 3] = f2pack(Q4, xy4);
                        ull   s4b = f2add(f2fma(e_m1, F2NEG1, s4), e1);
                        float Q4b  = Q4 - fmaf(xa,xa, ya*ya) + fmaf(xe,xe, ye*ye);
                        float xy4b = fmaf(xe, ye, fmaf(-xa, ya, xy4));
                        h4s1[u & 3] = s4b;
                        h4m1[u & 3] = f2pack(Q4b, xy4b);
                    }

                    // ---- emit output row i ----
                    if (i >= i0 && i < i1) {
                        float Sx, Sy, Qv, xyv, D0, D1;
                        // k=2 from raw rows i-1 (slot (u+4)&7), i ((u+5)&7): 2x LDS.128 each
                        const ulonglong2* ra_ = raw2 + ((u + 4) & 7) * RAW_SLOT + t;
                        const ulonglong2* rb_ = raw2 + ((u + 5) & 7) * RAW_SLOT + t;
                        ulonglong2 qa1 = ra_[1], qa2 = ra_[2];
                        ulonglong2 qb1 = rb_[1], qb2 = rb_[2];
                        ull a_om1 = qa1.y, a_e0 = qa2.x, a_o0 = qa2.y;
                        ull b_om1 = qb1.y, b_e0 = qb2.x, b_o0 = qb2.y;
                        float axa,aya,axb,ayb,axc,ayc,bxa,bya,bxb,byb,bxc,byc;
                        f2unpack(a_om1,axa,aya); f2unpack(a_e0,axb,ayb); f2unpack(a_o0,axc,ayc);
                        f2unpack(b_om1,bxa,bya); f2unpack(b_e0,bxb,byb); f2unpack(b_o0,bxc,byc);

                        ull s2 = f2add(f2add(a_om1, a_e0), f2add(b_om1, b_e0));
                        ull sq2 = f2fma(a_om1,a_om1, f2fma(a_e0,a_e0,
                                  f2fma(b_om1,b_om1, f2mul(b_e0,b_e0))));
                        float Q20  = hadd(sq2);
                        float xy20 = fmaf(axa,aya, fmaf(axb,ayb, fmaf(bxa,bya, bxb*byb)));
                        ull s2b = f2add(f2add(a_e0, a_o0), f2add(b_e0, b_o0));
                        ull sq2b = f2fma(a_e0,a_e0, f2fma(a_o0,a_o0,
                                   f2fma(b_e0,b_e0, f2mul(b_o0,b_o0))));
                        float Q21  = hadd(sq2b);
                        float xy21 = fmaf(axb,ayb, fmaf(axc,ayc, fmaf(bxb,byb, bxc*byc)));

                        f2unpack(s2, Sx, Sy);
                        float N0 = ssim_nd(Sx, Sy, Q20, xy20, 4.f, c1_2, c2_2, D0);
                        f2unpack(s2b, Sx, Sy);
                        float N1 = ssim_nd(Sx, Sy, Q21, xy21, 4.f, c1_2, c2_2, D1) * msk1;
                        acc2 += __fdividef(fmaf(N0, D1, N1 * D0), D0 * D1);

                        // k=4 resum of reg ring
                        ull ss = f2add(f2add(h4s0[0], h4s0[1]), f2add(h4s0[2], h4s0[3]));
                        ull mm = f2add(f2add(h4m0[0], h4m0[1]), f2add(h4m0[2], h4m0[3]));
                        f2unpack(ss, Sx, Sy); f2unpack(mm, Qv, xyv);
                        N0 = ssim_nd(Sx, Sy, Qv, xyv, 16.f, c1_4, c2_4, D0);
                        ss = f2add(f2add(h4s1[0], h4s1[1]), f2add(h4s1[2], h4s1[3]));
                        mm = f2add(f2add(h4m1[0], h4m1[1]), f2add(h4m1[2], h4m1[3]));
                        f2unpack(ss, Sx, Sy); f2unpack(mm, Qv, xyv);
                        N1 = ssim_nd(Sx, Sy, Qv, xyv, 16.f, c1_4, c2_4, D1) * msk1;
                        acc4 += __fdividef(fmaf(N0, D1, N1 * D0), D0 * D1);

                        if (full && i < HH) {
                            f2unpack(v7s0, Sx, Sy); f2unpack(v7m0, Qv, xyv);
                            N0 = ssim_nd(Sx, Sy, Qv, xyv, 49.f, c1_7, c2_7, D0);
                            accL += fabsf(Sx - Sy);
                            f2unpack(v7s1, Sx, Sy); f2unpack(v7m1, Qv, xyv);
                            N1 = ssim_nd(Sx, Sy, Qv, xyv, 49.f, c1_7, c2_7, D1);
                            accL += fabsf(Sx - Sy);
                            acc7 += __fdividef(fmaf(N0, D1, N1 * D0), D0 * D1);
                        }
                    }
                }
            }
            cxA = pxA; cyA = pyA; cxB = pxB; cyB = pyB;
        }
    }

    // ---------------- deterministic block reduction ----------------
    #pragma unroll
    for (int o = 16; o > 0; o >>= 1) {
        acc1 += __shfl_down_sync(0xFFFFFFFFu, acc1, o);
        acc2 += __shfl_down_sync(0xFFFFFFFFu, acc2, o);
        acc4 += __shfl_down_sync(0xFFFFFFFFu, acc4, o);
        acc7 += __shfl_down_sync(0xFFFFFFFFu, acc7, o);
        accL += __shfl_down_sync(0xFFFFFFFFu, accL, o);
    }
    __syncthreads();
    const int w = tid >> 5, lane = tid & 31;
    if (lane == 0) {
        red[w*5 + 0] = acc1; red[w*5 + 1] = acc2; red[w*5 + 2] = acc4;
        red[w*5 + 3] = acc7; red[w*5 + 4] = accL;
    }
    __syncthreads();
    if (tid == 0) {
        float s0 = 0.f, s1 = 0.f, s2 = 0.f, s3 = 0.f, s4 = 0.f;
        for (int ww = 0; ww < 7; ++ww) {
            s0 += red[ww*5 + 0]; s1 += red[ww*5 + 1]; s2 += red[ww*5 + 2];
            s3 += red[ww*5 + 3]; s4 += red[ww*5 + 4];
        }
        const int pb = (b * STRIPS + blockIdx.x) * 5;
        g_part[pb + 0] = s0; g_part[pb + 1] = s1; g_part[pb + 2] = s2;
        g_part[pb + 3] = s3; g_part[pb + 4] = s4;
    }
}

__global__ void msssim_reduce_kernel(float* __restrict__ out)
{
    __shared__ double red[256][5];
    double a0 = 0, a1 = 0, a2 = 0, a3 = 0, a4 = 0;
    for (int idx = threadIdx.x; idx < NPART; idx += 256) {
        a0 += (double)g_part[idx*5 + 0];
        a1 += (double)g_part[idx*5 + 1];
        a2 += (double)g_part[idx*5 + 2];
        a3 += (double)g_part[idx*5 + 3];
        a4 += (double)g_part[idx*5 + 4];
    }
    red[threadIdx.x][0] = a0; red[threadIdx.x][1] = a1; red[threadIdx.x][2] = a2;
    red[threadIdx.x][3] = a3; red[threadIdx.x][4] = a4;
    __syncthreads();
    for (int s = 128; s > 0; s >>= 1) {
        if (threadIdx.x < s) {
            #pragma unroll
            for (int q = 0; q < 5; ++q) red[threadIdx.x][q] += red[threadIdx.x + s][q];
        }
        __syncthreads();
    }
    if (threadIdx.x == 0) {
        const double n384 = (double)BATCH * 384.0 * 384.0;
        const double n385 = (double)BATCH * 385.0 * 385.0;
        double m1 = red[0][0] / n384;
        double m2 = red[0][1] / n385;
        double m4 = red[0][2] / n385;
        double m7 = red[0][3] / n384;
        double l1 = red[0][4] / (49.0 * n384);
        double loss = 0.84 * (1.0 - m1 * m2 * m4 * m7) + 0.16 * l1;
        out[0] = (float)loss;
    }
}

// one pad launch keeps ncu's "-s 5 -c 1" landing on the MAIN kernel
__global__ void msssim_noop_kernel() {}

extern "C" void kernel_launch(void* const* d_in, const int* in_sizes, int n_in,
                              void* d_out, int out_size)
{
    (void)in_sizes; (void)n_in; (void)out_size;
    const float* X  = (const float*)d_in[0];
    const float* Y  = (const float*)d_in[1];
    const float* DR = (const float*)d_in[2];

    cudaFuncSetAttribute(msssim_main_kernel,
                         cudaFuncAttributeMaxDynamicSharedMemorySize, SMEM_BYTES);

    dim3 grid(STRIPS, BATCH);
    msssim_main_kernel<<<grid, NTHREADS, SMEM_BYTES>>>(X, Y, DR);
    msssim_reduce_kernel<<<1, 256>>>((float*)d_out);
    msssim_noop_kernel<<<1, 32>>>();
}